// round 16
// baseline (speedup 1.0000x reference)
#include <cuda_runtime.h>
#include <cuda_bf16.h>
#include <cuda_fp16.h>
#include <math.h>
#include <stdint.h>

// ---------------- problem constants ----------------
#define S_LEN   50
#define T_LEN   50
#define BATCH   32
#define E_DIM   620
#define ECH     1000
#define H_DIM   1000
#define A_DIM   2000
#define V_DIM   30000
#define G_DIM   3000
#define C2_DIM  3620
#define NSTEPS  49
#define ROWS    (NSTEPS*BATCH)   // 1568

// ug layout: (BATCH, 4096): u in [0,1000), gh in [1024, 4024)
#define UG_LD   4096
#define UG_GH   1024

// ---------------- HMMA tiling ----------------
#define BM   128
#define BN   128
#define BK   32
#define LDSROW 40                        // b16 elems per smem row (80 B), bf16 kernel
#define TILE_BYTES (128*LDSROW*2)        // 10240
#define STAGE_BYTES (4*TILE_BYTES)       // 40960 (bf16 3-product kernel)
#define GEMM_SMEM (2*STAGE_BYTES)        // 81920

// fp16 kernel: BK=64, 144B row stride (conflict-free ldmatrix)
#define BK2  64
#define LDSROW2 72                       // fp16 elems per row (144 B)
#define TILE2_BYTES (128*LDSROW2*2)      // 18432
#define STAGE2_BYTES (2*TILE2_BYTES)     // 36864
#define GEMM2_SMEM (2*STAGE2_BYTES)      // 73728 (2-stage)

// big prediction GEMM padded dims
#define MPAD 1664                        // 13*128
#define NPAD 30080                       // 235*128
#define KPAD 3648                        // 57*64

// ---------------- fp32 scratch ----------------
#define OFF_ATT_PRE 0           // (S*B, H)
#define OFF_ANN_IH  1600000     // (S*B, 3H)
#define OFF_GI_E    6400000     // (ROWS, 3H)
#define OFF_H       11104000    // (50, B, H)
#define OFF_COMB2   12704000    // (ROWS, 3620)
#define OFF_UG      18380160    // (B, 4096)
#define OFF_SCORES  18511232    // (S, B)
#define SCRATCH_FLOATS 18512832

__device__ __align__(16) float g_scratch[SCRATCH_FLOATS];

// fp16 operands for the prediction GEMM: A single, B single
__device__ __align__(16) __half g_aF[(size_t)MPAD * KPAD];
__device__ __align__(16) __half g_bF[(size_t)NPAD * KPAD];

// bf16 hi/lo buffers for recurrence-path GEMMs
__device__ __align__(16) __nv_bfloat16 g_annS[2][1664 * 2048];
__device__ __align__(16) __nv_bfloat16 g_wcaS[2][1024 * 2048];
__device__ __align__(16) __nv_bfloat16 g_wihcS[2][3072 * 2048];
__device__ __align__(16) __nv_bfloat16 g_wiheS[2][3072 * 640];
__device__ __align__(16) __nv_bfloat16 g_embS[2][1664 * 640];
__device__ __align__(16) __nv_bfloat16 g_wstepS[2][4096 * 1024];

// ---------------- helpers ----------------
__device__ __forceinline__ float warp_sum(float v) {
#pragma unroll
    for (int o = 16; o; o >>= 1) v += __shfl_xor_sync(0xffffffffu, v, o);
    return v;
}
__device__ __forceinline__ float warp_max(float v) {
#pragma unroll
    for (int o = 16; o; o >>= 1) v = fmaxf(v, __shfl_xor_sync(0xffffffffu, v, o));
    return v;
}
__device__ __forceinline__ float tanh_fast(float x) {
    float y;
    asm("tanh.approx.f32 %0, %1;" : "=f"(y) : "f"(x));
    return y;
}
__device__ __forceinline__ uint32_t smem_u32(const void* p) {
    uint32_t a;
    asm("{ .reg .u64 t; cvta.to.shared.u64 t, %1; cvt.u32.u64 %0, t; }" : "=r"(a) : "l"(p));
    return a;
}
__device__ __forceinline__ void ldsm_x4(uint32_t* r, uint32_t addr) {
    asm volatile("ldmatrix.sync.aligned.m8n8.x4.shared.b16 {%0,%1,%2,%3}, [%4];"
        : "=r"(r[0]), "=r"(r[1]), "=r"(r[2]), "=r"(r[3]) : "r"(addr));
}
__device__ __forceinline__ void mma_bf16(float* c, const uint32_t* a, const uint32_t* b) {
    asm volatile(
        "mma.sync.aligned.m16n8k16.row.col.f32.bf16.bf16.f32 "
        "{%0,%1,%2,%3}, {%4,%5,%6,%7}, {%8,%9}, {%0,%1,%2,%3};"
        : "+f"(c[0]), "+f"(c[1]), "+f"(c[2]), "+f"(c[3])
        : "r"(a[0]), "r"(a[1]), "r"(a[2]), "r"(a[3]), "r"(b[0]), "r"(b[1]));
}
__device__ __forceinline__ void mma_f16(float* c, const uint32_t* a, const uint32_t* b) {
    asm volatile(
        "mma.sync.aligned.m16n8k16.row.col.f32.f16.f16.f32 "
        "{%0,%1,%2,%3}, {%4,%5,%6,%7}, {%8,%9}, {%0,%1,%2,%3};"
        : "+f"(c[0]), "+f"(c[1]), "+f"(c[2]), "+f"(c[3])
        : "r"(a[0]), "r"(a[1]), "r"(a[2]), "r"(a[3]), "r"(b[0]), "r"(b[1]));
}

// ================= splits =================
// bf16 hi/lo (recurrence path)
__global__ void split_gen4(const float* __restrict__ src, int ldsrc, int M, int K, int Kp,
                           __nv_bfloat16* __restrict__ hi, __nv_bfloat16* __restrict__ lo)
{
    int k4 = (blockIdx.x * 256 + threadIdx.x) * 4;
    int m = blockIdx.y;
    if (k4 >= Kp) return;
    float4 v = make_float4(0.f, 0.f, 0.f, 0.f);
    if (m < M && k4 < K)
        v = *reinterpret_cast<const float4*>(src + (size_t)m * ldsrc + k4);
    __nv_bfloat16 h0 = __float2bfloat16(v.x), h1 = __float2bfloat16(v.y);
    __nv_bfloat16 h2 = __float2bfloat16(v.z), h3 = __float2bfloat16(v.w);
    __nv_bfloat162 hp0(h0, h1), hp1(h2, h3);
    __nv_bfloat162 lp0(__float2bfloat16(v.x - __bfloat162float(h0)),
                       __float2bfloat16(v.y - __bfloat162float(h1)));
    __nv_bfloat162 lp1(__float2bfloat16(v.z - __bfloat162float(h2)),
                       __float2bfloat16(v.w - __bfloat162float(h3)));
    size_t o = (size_t)m * Kp + k4;
    *reinterpret_cast<__nv_bfloat162*>(hi + o)     = hp0;
    *reinterpret_cast<__nv_bfloat162*>(hi + o + 2) = hp1;
    *reinterpret_cast<__nv_bfloat162*>(lo + o)     = lp0;
    *reinterpret_cast<__nv_bfloat162*>(lo + o + 2) = lp1;
}

// fp16 single, 8 elems/thread
__global__ void split_f16(const float* __restrict__ src, int ldsrc, int M, int K, int Kp,
                          __half* __restrict__ out)
{
    int k8 = (blockIdx.x * 256 + threadIdx.x) * 8;
    int m = blockIdx.y;
    if (k8 >= Kp) return;
    float4 v0 = make_float4(0.f, 0.f, 0.f, 0.f);
    float4 v1 = make_float4(0.f, 0.f, 0.f, 0.f);
    if (m < M) {
        const float* base = src + (size_t)m * ldsrc;
        if (k8 < K)     v0 = *reinterpret_cast<const float4*>(base + k8);
        if (k8 + 4 < K) v1 = *reinterpret_cast<const float4*>(base + k8 + 4);
    }
    __half2 a(__float2half_rn(v0.x), __float2half_rn(v0.y));
    __half2 b(__float2half_rn(v0.z), __float2half_rn(v0.w));
    __half2 c(__float2half_rn(v1.x), __float2half_rn(v1.y));
    __half2 d(__float2half_rn(v1.z), __float2half_rn(v1.w));
    uint4 pk;
    pk.x = *reinterpret_cast<uint32_t*>(&a);
    pk.y = *reinterpret_cast<uint32_t*>(&b);
    pk.z = *reinterpret_cast<uint32_t*>(&c);
    pk.w = *reinterpret_cast<uint32_t*>(&d);
    *reinterpret_cast<uint4*>(out + (size_t)m * Kp + k8) = pk;
}

// ================= bf16 3-product HMMA GEMM (recurrence precompute) ============
__global__ __launch_bounds__(256)
void hmma_gemm(const __nv_bfloat16* __restrict__ Ah, const __nv_bfloat16* __restrict__ Al,
               const __nv_bfloat16* __restrict__ Bh, const __nv_bfloat16* __restrict__ Bl,
               int ldka, int ldkb, int kchunks,
               const float* __restrict__ bias, float* __restrict__ out, int ldo,
               int Mlim, int Nlim)
{
    extern __shared__ __align__(16) char smem[];
    const uint32_t sb = smem_u32(smem);
    const int tid = threadIdx.x;
    const int lane = tid & 31;
    const int wid = tid >> 5;
    const int wm = wid & 1;
    const int wn = wid >> 1;
    const int m0 = blockIdx.x * BM;
    const int n0 = blockIdx.y * BN;

    const __nv_bfloat16* srcs[4] = {
        Ah + (size_t)m0 * ldka, Al + (size_t)m0 * ldka,
        Bh + (size_t)n0 * ldkb, Bl + (size_t)n0 * ldkb
    };
    const int lds[4] = { ldka, ldka, ldkb, ldkb };

    auto load_stage = [&](int c, int buf) {
        uint32_t base = sb + buf * STAGE_BYTES;
        int kofs = c * BK;
#pragma unroll
        for (int i = 0; i < 8; i++) {
            int idx = tid + i * 256;
            int tile = idx >> 9;
            int rem = idx & 511;
            int row = rem >> 2;
            int seg = rem & 3;
            const char* g = (const char*)(srcs[tile] + (size_t)row * lds[tile] + kofs) + seg * 16;
            uint32_t so = base + tile * TILE_BYTES + row * (LDSROW * 2) + seg * 16;
            asm volatile("cp.async.cg.shared.global [%0], [%1], 16;\n" :: "r"(so), "l"(g));
        }
        asm volatile("cp.async.commit_group;\n" ::: "memory");
    };

    float acc[4][4][4];
#pragma unroll
    for (int i = 0; i < 4; i++)
#pragma unroll
        for (int j = 0; j < 4; j++)
#pragma unroll
            for (int q = 0; q < 4; q++) acc[i][j][q] = 0.f;

    load_stage(0, 0);

    for (int c = 0; c < kchunks; c++) {
        if (c + 1 < kchunks) {
            load_stage(c + 1, (c + 1) & 1);
            asm volatile("cp.async.wait_group 1;\n" ::: "memory");
        } else {
            asm volatile("cp.async.wait_group 0;\n" ::: "memory");
        }
        __syncthreads();

        uint32_t st = sb + (c & 1) * STAGE_BYTES;
        uint32_t bAh = st;
        uint32_t bAl = st + TILE_BYTES;
        uint32_t bBh = st + 2 * TILE_BYTES;
        uint32_t bBl = st + 3 * TILE_BYTES;

#pragma unroll
        for (int ks = 0; ks < 2; ks++) {
            uint32_t ah[4][4], al[4][4], bh[4][2], bl[4][2];

            int arow = wm * 64 + (lane & 15);
            uint32_t acol = ks * 32 + (lane >> 4) * 16;
#pragma unroll
            for (int mt = 0; mt < 4; mt++) {
                uint32_t off = (uint32_t)(arow + mt * 16) * (LDSROW * 2) + acol;
                ldsm_x4(ah[mt], bAh + off);
                ldsm_x4(al[mt], bAl + off);
            }
            int brow_base = wn * 32 + (lane & 7) + ((lane >> 4) << 3);
            uint32_t bcol = ks * 32 + ((lane >> 3) & 1) * 16;
#pragma unroll
            for (int np = 0; np < 2; np++) {
                uint32_t r[4];
                uint32_t off = (uint32_t)(brow_base + np * 16) * (LDSROW * 2) + bcol;
                ldsm_x4(r, bBh + off);
                bh[np * 2][0] = r[0]; bh[np * 2][1] = r[1];
                bh[np * 2 + 1][0] = r[2]; bh[np * 2 + 1][1] = r[3];
                ldsm_x4(r, bBl + off);
                bl[np * 2][0] = r[0]; bl[np * 2][1] = r[1];
                bl[np * 2 + 1][0] = r[2]; bl[np * 2 + 1][1] = r[3];
            }
#pragma unroll
            for (int mt = 0; mt < 4; mt++)
#pragma unroll
                for (int nt = 0; nt < 4; nt++) {
                    mma_bf16(acc[mt][nt], ah[mt], bh[nt]);
                    mma_bf16(acc[mt][nt], al[mt], bh[nt]);
                    mma_bf16(acc[mt][nt], ah[mt], bl[nt]);
                }
        }
        __syncthreads();
    }

#pragma unroll
    for (int mt = 0; mt < 4; mt++) {
#pragma unroll
        for (int nt = 0; nt < 4; nt++) {
            int m = m0 + wm * 64 + mt * 16 + (lane >> 2);
            int n = n0 + wn * 32 + nt * 8 + 2 * (lane & 3);
            if (n < Nlim) {
                float b0 = 0.f, b1 = 0.f;
                if (bias) { b0 = bias[n]; b1 = bias[n + 1]; }
                if (m < Mlim) {
                    float2 v = make_float2(acc[mt][nt][0] + b0, acc[mt][nt][1] + b1);
                    *reinterpret_cast<float2*>(out + (size_t)m * ldo + n) = v;
                }
                if (m + 8 < Mlim) {
                    float2 v = make_float2(acc[mt][nt][2] + b0, acc[mt][nt][3] + b1);
                    *reinterpret_cast<float2*>(out + (size_t)(m + 8) * ldo + n) = v;
                }
            }
        }
    }
}

// ================= fp16 single-product HMMA GEMM, BK=64, 2-stage ===============
__global__ __launch_bounds__(256)
void hmma_gemm_f16(const __half* __restrict__ A, const __half* __restrict__ B,
                   int kchunks,
                   const float* __restrict__ bias, float* __restrict__ out, int ldo,
                   int Mlim, int Nlim)
{
    extern __shared__ __align__(16) char smem[];
    const uint32_t sb = smem_u32(smem);
    const int tid = threadIdx.x;
    const int lane = tid & 31;
    const int wid = tid >> 5;
    const int wm = wid & 1;
    const int wn = wid >> 1;
    const int m0 = blockIdx.x * BM;
    const int n0 = blockIdx.y * BN;

    const __half* srcs[2] = {
        A + (size_t)m0 * KPAD, B + (size_t)n0 * KPAD
    };

    auto load_stage = [&](int c, int buf) {
        uint32_t base = sb + buf * STAGE2_BYTES;
        int kofs = c * BK2;
#pragma unroll
        for (int i = 0; i < 8; i++) {
            int idx = tid + i * 256;            // 0..2047
            int tile = idx >> 10;
            int rem = idx & 1023;
            int row = rem >> 3;
            int seg = rem & 7;
            const char* g = (const char*)(srcs[tile] + (size_t)row * KPAD + kofs) + seg * 16;
            uint32_t so = base + tile * TILE2_BYTES + row * (LDSROW2 * 2) + seg * 16;
            asm volatile("cp.async.cg.shared.global [%0], [%1], 16;\n" :: "r"(so), "l"(g));
        }
        asm volatile("cp.async.commit_group;\n" ::: "memory");
    };

    float acc[4][4][4];
#pragma unroll
    for (int i = 0; i < 4; i++)
#pragma unroll
        for (int j = 0; j < 4; j++)
#pragma unroll
            for (int q = 0; q < 4; q++) acc[i][j][q] = 0.f;

    load_stage(0, 0);

    for (int c = 0; c < kchunks; c++) {
        if (c + 1 < kchunks) {
            load_stage(c + 1, (c + 1) & 1);
            asm volatile("cp.async.wait_group 1;\n" ::: "memory");
        } else {
            asm volatile("cp.async.wait_group 0;\n" ::: "memory");
        }
        __syncthreads();

        uint32_t st = sb + (c & 1) * STAGE2_BYTES;
        uint32_t bA = st;
        uint32_t bB = st + TILE2_BYTES;

#pragma unroll
        for (int ks = 0; ks < 4; ks++) {
            uint32_t ah[4][4], bh[4][2];

            int arow = wm * 64 + (lane & 15);
            uint32_t acol = ks * 32 + (lane >> 4) * 16;
#pragma unroll
            for (int mt = 0; mt < 4; mt++) {
                uint32_t off = (uint32_t)(arow + mt * 16) * (LDSROW2 * 2) + acol;
                ldsm_x4(ah[mt], bA + off);
            }
            int brow_base = wn * 32 + (lane & 7) + ((lane >> 4) << 3);
            uint32_t bcol = ks * 32 + ((lane >> 3) & 1) * 16;
#pragma unroll
            for (int np = 0; np < 2; np++) {
                uint32_t r[4];
                uint32_t off = (uint32_t)(brow_base + np * 16) * (LDSROW2 * 2) + bcol;
                ldsm_x4(r, bB + off);
                bh[np * 2][0] = r[0]; bh[np * 2][1] = r[1];
                bh[np * 2 + 1][0] = r[2]; bh[np * 2 + 1][1] = r[3];
            }
#pragma unroll
            for (int mt = 0; mt < 4; mt++)
#pragma unroll
                for (int nt = 0; nt < 4; nt++)
                    mma_f16(acc[mt][nt], ah[mt], bh[nt]);
        }
        __syncthreads();
    }

#pragma unroll
    for (int mt = 0; mt < 4; mt++) {
#pragma unroll
        for (int nt = 0; nt < 4; nt++) {
            int m = m0 + wm * 64 + mt * 16 + (lane >> 2);
            int n = n0 + wn * 32 + nt * 8 + 2 * (lane & 3);
            if (n < Nlim) {
                float b0 = bias[n], b1 = bias[n + 1];
                if (m < Mlim) {
                    float2 v = make_float2(acc[mt][nt][0] + b0, acc[mt][nt][1] + b1);
                    *reinterpret_cast<float2*>(out + (size_t)m * ldo + n) = v;
                }
                if (m + 8 < Mlim) {
                    float2 v = make_float2(acc[mt][nt][2] + b0, acc[mt][nt][3] + b1);
                    *reinterpret_cast<float2*>(out + (size_t)(m + 8) * ldo + n) = v;
                }
            }
        }
    }
}

// ---------------- init ----------------
__global__ void zero_kernel(float* __restrict__ preds, float* __restrict__ attns)
{
    int i = blockIdx.x * blockDim.x + threadIdx.x;
    if (i < BATCH * V_DIM) preds[i] = 0.f;
    if (i < S_LEN * BATCH) attns[i] = 0.f;
}

// ---------------- gather embeddings into comb2 emb columns ----------------
__global__ void gather_kernel(const int* __restrict__ tokens,
                              const float* __restrict__ emb,
                              float* __restrict__ comb2)
{
    int r = blockIdx.x;
    int tok = tokens[r];
    const float4* src = reinterpret_cast<const float4*>(emb + (size_t)tok * E_DIM);
    float4* dst = reinterpret_cast<float4*>(comb2 + (size_t)r * C2_DIM);
    int i = threadIdx.x;
    if (i < E_DIM / 4) dst[i] = src[i];
}

// ---------------- h0 = tanh(ann[0,:,ECH:] @ W_h.T + b_h) ----------------
__global__ void h0_kernel(const float* __restrict__ ann, const float* __restrict__ W_h,
                          const float* __restrict__ b_h, float* __restrict__ hbuf,
                          float* __restrict__ comb2)
{
    int w = (blockIdx.x * 256 + threadIdx.x) >> 5;
    if (w >= BATCH * H_DIM) return;
    int lane = threadIdx.x & 31;
    int b = w / H_DIM, n = w - b * H_DIM;
    const float4* a4 = reinterpret_cast<const float4*>(ann + (size_t)b * A_DIM + ECH);
    const float4* w4 = reinterpret_cast<const float4*>(W_h + (size_t)n * H_DIM);
    float s = 0.f;
    for (int i = lane; i < H_DIM / 4; i += 32) {
        float4 x = a4[i], y = w4[i];
        s += x.x * y.x + x.y * y.y + x.z * y.z + x.w * y.w;
    }
    s = warp_sum(s);
    if (lane == 0) {
        float v = tanh_fast(s + b_h[n]);
        hbuf[b * H_DIM + n] = v;
        comb2[(size_t)b * C2_DIM + E_DIM + n] = v;
    }
}

// ---------------- per-step: ug = h @ [Wc_h | W_hh].T ----------------
// 256 threads (8 warps) x 4 rows/warp: per-block smem traffic halves vs 2-row,
// grid 125 = one wave, 4000 rows exactly. Per-row FMA k-order unchanged.
#define STEP_SMEM (BATCH * H_DIM * 4)    // 128000 B
__global__ __launch_bounds__(256)
void step_ug3_kernel(const __nv_bfloat16* __restrict__ wh, const __nv_bfloat16* __restrict__ wl,
                     const float* __restrict__ h, float* __restrict__ ug)
{
    extern __shared__ float hsh[];       // [BATCH * H_DIM]
    int tid = threadIdx.x;
    int lane = tid & 31;
    int warp = tid >> 5;                 // 0..7

    const float4* h4 = reinterpret_cast<const float4*>(h);
    float4* s4 = reinterpret_cast<float4*>(hsh);
    for (int i = tid; i < BATCH * H_DIM / 4; i += 256) s4[i] = h4[i];
    __syncthreads();

    int t = blockIdx.x * 8 + warp;       // 0..999
    int r0 = t * 4;                      // rows r0..r0+3, all < 4000
    int n[4];
    const __nv_bfloat16 *WH[4], *WL[4];
#pragma unroll
    for (int j = 0; j < 4; j++) {
        int r = r0 + j;
        n[j] = (r < 1000) ? r : (r + 24);
        WH[j] = wh + (size_t)n[j] * 1024;
        WL[j] = wl + (size_t)n[j] * 1024;
    }

    float acc[4][32];
#pragma unroll
    for (int j = 0; j < 4; j++)
#pragma unroll
        for (int b = 0; b < 32; b++) acc[j][b] = 0.f;

    for (int k = lane; k < H_DIM; k += 32) {
        float w[4];
#pragma unroll
        for (int j = 0; j < 4; j++)
            w[j] = __bfloat162float(WH[j][k]) + __bfloat162float(WL[j][k]);
        const float* hp = hsh + k;
#pragma unroll
        for (int b = 0; b < 32; b++) {
            float hv = hp[b * H_DIM];
#pragma unroll
            for (int j = 0; j < 4; j++)
                acc[j][b] = fmaf(w[j], hv, acc[j][b]);
        }
    }

#pragma unroll
    for (int j = 0; j < 4; j++) {
        float out = 0.f;
#pragma unroll
        for (int b = 0; b < 32; b++) {
            float s = warp_sum(acc[j][b]);
            if (lane == b) out = s;
        }
        ug[(size_t)lane * UG_LD + n[j]] = out;
    }
}

// ---------------- per-step: scores ----------------
__global__ void scores_kernel(const float* __restrict__ att_pre,
                              const float* __restrict__ ug,
                              const float* __restrict__ w_a,
                              float* __restrict__ scores)
{
    int w = (blockIdx.x * blockDim.x + threadIdx.x) >> 5;
    if (w >= S_LEN * BATCH) return;
    int lane = threadIdx.x & 31;
    int b = w & 31;
    const float4* ap = reinterpret_cast<const float4*>(att_pre + (size_t)w * H_DIM);
    const float4* ub = reinterpret_cast<const float4*>(ug + (size_t)b * UG_LD);
    const float4* wa = reinterpret_cast<const float4*>(w_a);
    float s = 0.f;
    for (int i = lane; i < H_DIM / 4; i += 32) {
        float4 p = ap[i], q = ub[i], wv = wa[i];
        s += wv.x * tanh_fast(p.x + q.x) + wv.y * tanh_fast(p.y + q.y)
           + wv.z * tanh_fast(p.z + q.z) + wv.w * tanh_fast(p.w + q.w);
    }
    s = warp_sum(s);
    if (lane == 0) scores[w] = s;
}

// ---------------- per-step fused: softmax + context + GRU gates ----------------
__global__ __launch_bounds__(256)
void ctxgates_kernel(const float* __restrict__ scores,
                     const float* __restrict__ ann,
                     float* __restrict__ attn_out,
                     float* __restrict__ ctx_out,
                     const float* __restrict__ ann_ih,
                     const float* __restrict__ gi_e_t,
                     const float* __restrict__ ug,
                     const float* __restrict__ b_hh,
                     const float* __restrict__ hprev,
                     float* __restrict__ hnew,
                     float* __restrict__ comb2_hnext)   // nullptr on last step
{
    __shared__ float attn_sh[S_LEN * BATCH];
    int tid = threadIdx.x;
    int bid = blockIdx.x;
    int warp = tid >> 5, lane = tid & 31;

    for (int s = warp; s < S_LEN; s += 8) {
        float v = scores[s * BATCH + lane];
        float mx = warp_max(v);
        float e = __expf(v - mx);
        float sm = warp_sum(e);
        float a = e / sm;
        attn_sh[s * BATCH + lane] = a;
        if (bid == 0) attn_out[s * BATCH + lane] = a;
    }
    __syncthreads();

    if (bid < 64) {
#pragma unroll
        for (int r = 0; r < 4; r++) {
            int local = r * 256 + tid;
            if (local < 1000) {
                int g = bid * 1000 + local;
                int b = g / A_DIM, e = g % A_DIM;
                float acc = 0.f;
#pragma unroll 10
                for (int s = 0; s < S_LEN; s++)
                    acc += attn_sh[s * BATCH + b] * ann[((size_t)s * BATCH + b) * A_DIM + e];
                ctx_out[(size_t)b * C2_DIM + (E_DIM + H_DIM) + e] = acc;
            }
        }
    } else {
        int gb = bid - 64;
        int b = gb & 31;
        int jc = gb >> 5;
        int j = jc * 256 + tid;
        if (j >= H_DIM) return;

        float gr = 0.f, gz = 0.f, gn = 0.f;
#pragma unroll 10
        for (int s = 0; s < S_LEN; s++) {
            float a = attn_sh[s * BATCH + b];
            const float* base = ann_ih + ((size_t)s * BATCH + b) * G_DIM;
            gr += a * base[j];
            gz += a * base[H_DIM + j];
            gn += a * base[2 * H_DIM + j];
        }
        const float* ge = gi_e_t + (size_t)b * G_DIM;
        const float* gb_ = ug + (size_t)b * UG_LD + UG_GH;
        float hr = gb_[j] + b_hh[j];
        float hz = gb_[H_DIM + j] + b_hh[H_DIM + j];
        float hn = gb_[2 * H_DIM + j] + b_hh[2 * H_DIM + j];
        float r = 1.f / (1.f + __expf(-(ge[j] + gr + hr)));
        float z = 1.f / (1.f + __expf(-(ge[H_DIM + j] + gz + hz)));
        float n = tanh_fast(ge[2 * H_DIM + j] + gn + r * hn);
        float hp = hprev[(size_t)b * H_DIM + j];
        float v = (1.f - z) * n + z * hp;
        hnew[(size_t)b * H_DIM + j] = v;
        if (comb2_hnext)
            comb2_hnext[(size_t)b * C2_DIM + E_DIM + j] = v;
    }
}

// ---------------- emit hidden output ----------------
__global__ void hidden_kernel(const float* __restrict__ hbuf, float* __restrict__ hidden)
{
    int i = blockIdx.x * blockDim.x + threadIdx.x;
    if (i < BATCH * H_DIM)
        hidden[i] = hbuf[(size_t)NSTEPS * BATCH * H_DIM + i];
}

// ---------------- single-pass row log-softmax ----------------
__global__ __launch_bounds__(512)
void logsoftmax_kernel(float* __restrict__ logits)
{
    extern __shared__ float sh[];
    int r = blockIdx.x;
    float* p = logits + (size_t)r * V_DIM;
    int tid = threadIdx.x;
    int lane = tid & 31, warp = tid >> 5;
    __shared__ float red[16];
    __shared__ float bc[2];

    float mx = -1e30f;
    for (int i = tid; i < V_DIM; i += 512) {
        float v = p[i];
        sh[i] = v;
        mx = fmaxf(mx, v);
    }
    mx = warp_max(mx);
    if (lane == 0) red[warp] = mx;
    __syncthreads();
    if (tid < 32) {
        float v = (tid < 16) ? red[tid] : -1e30f;
        v = warp_max(v);
        if (tid == 0) bc[0] = v;
    }
    __syncthreads();
    mx = bc[0];

    float sm = 0.f;
    for (int i = tid; i < V_DIM; i += 512) sm += __expf(sh[i] - mx);
    sm = warp_sum(sm);
    if (lane == 0) red[warp] = sm;
    __syncthreads();
    if (tid < 32) {
        float v = (tid < 16) ? red[tid] : 0.f;
        v = warp_sum(v);
        if (tid == 0) bc[1] = v;
    }
    __syncthreads();
    float lse = mx + logf(bc[1]);

    for (int i = tid; i < V_DIM; i += 512) p[i] = sh[i] - lse;
}

// ---------------- host launcher ----------------
extern "C" void kernel_launch(void* const* d_in, const int* in_sizes, int n_in,
                              void* d_out, int out_size)
{
    (void)in_sizes; (void)n_in; (void)out_size;
    const int*   tokens = (const int*)  d_in[0];
    const float* ann    = (const float*)d_in[1];
    const float* emb    = (const float*)d_in[2];
    const float* W_h    = (const float*)d_in[3];
    const float* b_h    = (const float*)d_in[4];
    const float* W_c    = (const float*)d_in[5];
    const float* b_c    = (const float*)d_in[6];
    const float* w_a    = (const float*)d_in[7];
    const float* W_ih   = (const float*)d_in[8];
    const float* W_hh   = (const float*)d_in[9];
    const float* b_ih   = (const float*)d_in[10];
    const float* b_hh   = (const float*)d_in[11];
    const float* W_p    = (const float*)d_in[12];
    const float* b_p    = (const float*)d_in[13];

    float* scr = nullptr;
    cudaGetSymbolAddress((void**)&scr, g_scratch);
    __half *aF, *bF;
    __nv_bfloat16 *annS, *wcaS, *wihcS, *wiheS, *embS, *wstepS;
    cudaGetSymbolAddress((void**)&aF,     g_aF);
    cudaGetSymbolAddress((void**)&bF,     g_bF);
    cudaGetSymbolAddress((void**)&annS,   g_annS);
    cudaGetSymbolAddress((void**)&wcaS,   g_wcaS);
    cudaGetSymbolAddress((void**)&wihcS,  g_wihcS);
    cudaGetSymbolAddress((void**)&wiheS,  g_wiheS);
    cudaGetSymbolAddress((void**)&embS,   g_embS);
    cudaGetSymbolAddress((void**)&wstepS, g_wstepS);

    __nv_bfloat16* annL  = annS  + (size_t)1664 * 2048;
    __nv_bfloat16* wcaL  = wcaS  + (size_t)1024 * 2048;
    __nv_bfloat16* wihcL = wihcS + (size_t)3072 * 2048;
    __nv_bfloat16* wiheL = wiheS + (size_t)3072 * 640;
    __nv_bfloat16* embL  = embS  + (size_t)1664 * 640;
    __nv_bfloat16* wstL  = wstepS + (size_t)4096 * 1024;

    float* att_pre = scr + OFF_ATT_PRE;
    float* ann_ih  = scr + OFF_ANN_IH;
    float* gi_e    = scr + OFF_GI_E;
    float* hbuf    = scr + OFF_H;
    float* comb2   = scr + OFF_COMB2;
    float* ug      = scr + OFF_UG;
    float* scbuf   = scr + OFF_SCORES;

    float* preds  = (float*)d_out;
    float* hidden = preds + (size_t)T_LEN * BATCH * V_DIM;
    float* attns  = hidden + BATCH * H_DIM;
    float* predsB = preds + (size_t)BATCH * V_DIM;

    // one-time resource init
    static cudaStream_t s2 = nullptr;
    static cudaEvent_t evFork, evB, evG1, evJoin;
    if (!s2) {
        cudaStreamCreateWithFlags(&s2, cudaStreamNonBlocking);
        cudaEventCreateWithFlags(&evFork, cudaEventDisableTiming);
        cudaEventCreateWithFlags(&evB, cudaEventDisableTiming);
        cudaEventCreateWithFlags(&evG1, cudaEventDisableTiming);
        cudaEventCreateWithFlags(&evJoin, cudaEventDisableTiming);
        cudaFuncSetAttribute(hmma_gemm,
                             cudaFuncAttributeMaxDynamicSharedMemorySize, GEMM_SMEM);
        cudaFuncSetAttribute(hmma_gemm_f16,
                             cudaFuncAttributeMaxDynamicSharedMemorySize, GEMM2_SMEM);
        cudaFuncSetAttribute(logsoftmax_kernel,
                             cudaFuncAttributeMaxDynamicSharedMemorySize, V_DIM * 4);
        cudaFuncSetAttribute(step_ug3_kernel,
                             cudaFuncAttributeMaxDynamicSharedMemorySize, STEP_SMEM);
    }

    // ---- fork: W_p -> fp16 on side stream (overlaps precompute phase) ----
    zero_kernel<<<(BATCH * V_DIM + 255) / 256, 256>>>(preds, attns);
    cudaEventRecord(evFork, 0);
    cudaStreamWaitEvent(s2, evFork, 0);
    split_f16<<<dim3(2, NPAD), 256, 0, s2>>>(W_p, C2_DIM, V_DIM, C2_DIM, KPAD, bF);
    cudaEventRecord(evB, s2);

    // ---- main stream: splits + h0 + precompute ----
    gather_kernel<<<ROWS, 160>>>(tokens, emb, comb2);
    split_gen4<<<dim3(2, 1664), 256>>>(ann, A_DIM, S_LEN * BATCH, A_DIM, 2048, annS, annL);
    split_gen4<<<dim3(2, 1024), 256>>>(W_c + H_DIM, H_DIM + A_DIM, H_DIM, A_DIM, 2048, wcaS, wcaL);
    split_gen4<<<dim3(2, 3072), 256>>>(W_ih + E_DIM, E_DIM + A_DIM, G_DIM, A_DIM, 2048, wihcS, wihcL);
    split_gen4<<<dim3(1, 3072), 256>>>(W_ih, E_DIM + A_DIM, G_DIM, E_DIM, 640, wiheS, wiheL);
    split_gen4<<<dim3(1, 1664), 256>>>(comb2, C2_DIM, ROWS, E_DIM, 640, embS, embL);
    split_gen4<<<dim3(1, 1024), 256>>>(W_c, H_DIM + A_DIM, H_DIM, H_DIM, 1024, wstepS, wstL);
    split_gen4<<<dim3(1, 3072), 256>>>(W_hh, H_DIM, G_DIM, H_DIM, 1024,
                                       wstepS + (size_t)1024 * 1024, wstL + (size_t)1024 * 1024);

    h0_kernel<<<4000, 256>>>(ann, W_h, b_h, hbuf, comb2);

    hmma_gemm<<<dim3(13, 8), 256, GEMM_SMEM>>>(annS, annL, wcaS, wcaL,
        2048, 2048, 64, b_c, att_pre, H_DIM, S_LEN * BATCH, H_DIM);
    hmma_gemm<<<dim3(13, 24), 256, GEMM_SMEM>>>(annS, annL, wihcS, wihcL,
        2048, 2048, 64, nullptr, ann_ih, G_DIM, S_LEN * BATCH, G_DIM);
    hmma_gemm<<<dim3(13, 24), 256, GEMM_SMEM>>>(embS, embL, wiheS, wiheL,
        640, 640, 20, b_ih, gi_e, G_DIM, ROWS, G_DIM);

    // ---- sequential recurrence (3 launches/step, single stream) ----
    for (int i = 0; i < NSTEPS; i++) {
        float* hprev = hbuf + (size_t)i * BATCH * H_DIM;
        float* hnext = hbuf + (size_t)(i + 1) * BATCH * H_DIM;
        float* attn_t = attns + (size_t)(i + 1) * S_LEN * BATCH;
        float* c2h = (i + 1 < NSTEPS) ? comb2 + (size_t)(i + 1) * BATCH * C2_DIM : nullptr;

        step_ug3_kernel<<<125, 256, STEP_SMEM>>>(wstepS, wstL, hprev, ug);
        scores_kernel<<<200, 256>>>(att_pre, ug, w_a, scbuf);
        ctxgates_kernel<<<192, 256>>>(scbuf, ann, attn_t,
                                      comb2 + (size_t)i * BATCH * C2_DIM,
                                      ann_ih, gi_e + (size_t)i * BATCH * G_DIM,
                                      ug, b_hh, hprev, hnext, c2h);
    }

    hidden_kernel<<<(BATCH * H_DIM + 255) / 256, 256>>>(hbuf, hidden);
    split_f16<<<dim3(2, 1664), 256>>>(comb2, C2_DIM, ROWS, C2_DIM, KPAD, aF);

    // ---- prediction GEMM in two M-halves; log-softmax of half 1 overlaps half 2 ----
    cudaStreamWaitEvent(0, evB, 0);          // B (W_p fp16) ready
    hmma_gemm_f16<<<dim3(6, 235), 256, GEMM2_SMEM>>>(aF, bF,
        KPAD / BK2, b_p, predsB, V_DIM, 768, V_DIM);
    cudaEventRecord(evG1, 0);

    hmma_gemm_f16<<<dim3(7, 235), 256, GEMM2_SMEM>>>(aF + (size_t)768 * KPAD, bF,
        KPAD / BK2, b_p, predsB + (size_t)768 * V_DIM, V_DIM, ROWS - 768, V_DIM);

    cudaStreamWaitEvent(s2, evG1, 0);
    logsoftmax_kernel<<<768, 512, V_DIM * 4, s2>>>(predsB);
    cudaEventRecord(evJoin, s2);

    logsoftmax_kernel<<<ROWS - 768, 512, V_DIM * 4>>>(predsB + (size_t)768 * V_DIM);
    cudaStreamWaitEvent(0, evJoin, 0);
}

// round 17
// speedup vs baseline: 1.0801x; 1.0801x over previous
#include <cuda_runtime.h>
#include <cuda_bf16.h>
#include <cuda_fp16.h>
#include <math.h>
#include <stdint.h>

// ---------------- problem constants ----------------
#define S_LEN   50
#define T_LEN   50
#define BATCH   32
#define E_DIM   620
#define ECH     1000
#define H_DIM   1000
#define A_DIM   2000
#define V_DIM   30000
#define G_DIM   3000
#define C2_DIM  3620
#define NSTEPS  49
#define ROWS    (NSTEPS*BATCH)   // 1568

// ug layout: (BATCH, 4096): u in [0,1000), gh in [1024, 4024)
#define UG_LD   4096
#define UG_GH   1024

// ---------------- HMMA tiling ----------------
#define BM   128
#define BN   128
#define BK   32
#define LDSROW 40                        // b16 elems per smem row (80 B), bf16 kernel
#define TILE_BYTES (128*LDSROW*2)        // 10240
#define STAGE_BYTES (4*TILE_BYTES)       // 40960 (bf16 3-product kernel)
#define GEMM_SMEM (2*STAGE_BYTES)        // 81920

// fp16 kernel: BK=64, 144B row stride (conflict-free ldmatrix)
#define BK2  64
#define LDSROW2 72                       // fp16 elems per row (144 B)
#define TILE2_BYTES (128*LDSROW2*2)      // 18432
#define STAGE2_BYTES (2*TILE2_BYTES)     // 36864
#define GEMM2_SMEM (2*STAGE2_BYTES)      // 73728 (2-stage)

// big prediction GEMM padded dims
#define MPAD 1664                        // 13*128
#define NPAD 30080                       // 235*128
#define KPAD 3648                        // 57*64

// ---------------- fp32 scratch ----------------
#define OFF_ATT_PRE 0           // (S*B, H)
#define OFF_ANN_IH  1600000     // (S*B, 3H)
#define OFF_GI_E    6400000     // (ROWS, 3H)
#define OFF_H       11104000    // (50, B, H)
#define OFF_COMB2   12704000    // (ROWS, 3620)
#define OFF_UG      18380160    // (B, 4096)
#define OFF_SCORES  18511232    // (S, B)
#define SCRATCH_FLOATS 18512832

__device__ __align__(16) float g_scratch[SCRATCH_FLOATS];

// fp16 operands for the prediction GEMM: A single, B single
__device__ __align__(16) __half g_aF[(size_t)MPAD * KPAD];
__device__ __align__(16) __half g_bF[(size_t)NPAD * KPAD];

// bf16 hi/lo buffers for recurrence-path GEMMs
__device__ __align__(16) __nv_bfloat16 g_annS[2][1664 * 2048];
__device__ __align__(16) __nv_bfloat16 g_wcaS[2][1024 * 2048];
__device__ __align__(16) __nv_bfloat16 g_wihcS[2][3072 * 2048];
__device__ __align__(16) __nv_bfloat16 g_wiheS[2][3072 * 640];
__device__ __align__(16) __nv_bfloat16 g_embS[2][1664 * 640];
__device__ __align__(16) __nv_bfloat16 g_wstepS[2][4096 * 1024];

// ---------------- helpers ----------------
__device__ __forceinline__ float warp_sum(float v) {
#pragma unroll
    for (int o = 16; o; o >>= 1) v += __shfl_xor_sync(0xffffffffu, v, o);
    return v;
}
__device__ __forceinline__ float warp_max(float v) {
#pragma unroll
    for (int o = 16; o; o >>= 1) v = fmaxf(v, __shfl_xor_sync(0xffffffffu, v, o));
    return v;
}
__device__ __forceinline__ float tanh_fast(float x) {
    float y;
    asm("tanh.approx.f32 %0, %1;" : "=f"(y) : "f"(x));
    return y;
}
__device__ __forceinline__ uint32_t smem_u32(const void* p) {
    uint32_t a;
    asm("{ .reg .u64 t; cvta.to.shared.u64 t, %1; cvt.u32.u64 %0, t; }" : "=r"(a) : "l"(p));
    return a;
}
__device__ __forceinline__ void ldsm_x4(uint32_t* r, uint32_t addr) {
    asm volatile("ldmatrix.sync.aligned.m8n8.x4.shared.b16 {%0,%1,%2,%3}, [%4];"
        : "=r"(r[0]), "=r"(r[1]), "=r"(r[2]), "=r"(r[3]) : "r"(addr));
}
__device__ __forceinline__ void mma_bf16(float* c, const uint32_t* a, const uint32_t* b) {
    asm volatile(
        "mma.sync.aligned.m16n8k16.row.col.f32.bf16.bf16.f32 "
        "{%0,%1,%2,%3}, {%4,%5,%6,%7}, {%8,%9}, {%0,%1,%2,%3};"
        : "+f"(c[0]), "+f"(c[1]), "+f"(c[2]), "+f"(c[3])
        : "r"(a[0]), "r"(a[1]), "r"(a[2]), "r"(a[3]), "r"(b[0]), "r"(b[1]));
}
__device__ __forceinline__ void mma_f16(float* c, const uint32_t* a, const uint32_t* b) {
    asm volatile(
        "mma.sync.aligned.m16n8k16.row.col.f32.f16.f16.f32 "
        "{%0,%1,%2,%3}, {%4,%5,%6,%7}, {%8,%9}, {%0,%1,%2,%3};"
        : "+f"(c[0]), "+f"(c[1]), "+f"(c[2]), "+f"(c[3])
        : "r"(a[0]), "r"(a[1]), "r"(a[2]), "r"(a[3]), "r"(b[0]), "r"(b[1]));
}

// ================= splits =================
// bf16 hi/lo (recurrence path)
__global__ void split_gen4(const float* __restrict__ src, int ldsrc, int M, int K, int Kp,
                           __nv_bfloat16* __restrict__ hi, __nv_bfloat16* __restrict__ lo)
{
    int k4 = (blockIdx.x * 256 + threadIdx.x) * 4;
    int m = blockIdx.y;
    if (k4 >= Kp) return;
    float4 v = make_float4(0.f, 0.f, 0.f, 0.f);
    if (m < M && k4 < K)
        v = *reinterpret_cast<const float4*>(src + (size_t)m * ldsrc + k4);
    __nv_bfloat16 h0 = __float2bfloat16(v.x), h1 = __float2bfloat16(v.y);
    __nv_bfloat16 h2 = __float2bfloat16(v.z), h3 = __float2bfloat16(v.w);
    __nv_bfloat162 hp0(h0, h1), hp1(h2, h3);
    __nv_bfloat162 lp0(__float2bfloat16(v.x - __bfloat162float(h0)),
                       __float2bfloat16(v.y - __bfloat162float(h1)));
    __nv_bfloat162 lp1(__float2bfloat16(v.z - __bfloat162float(h2)),
                       __float2bfloat16(v.w - __bfloat162float(h3)));
    size_t o = (size_t)m * Kp + k4;
    *reinterpret_cast<__nv_bfloat162*>(hi + o)     = hp0;
    *reinterpret_cast<__nv_bfloat162*>(hi + o + 2) = hp1;
    *reinterpret_cast<__nv_bfloat162*>(lo + o)     = lp0;
    *reinterpret_cast<__nv_bfloat162*>(lo + o + 2) = lp1;
}

// fp16 single, 8 elems/thread
__global__ void split_f16(const float* __restrict__ src, int ldsrc, int M, int K, int Kp,
                          __half* __restrict__ out)
{
    int k8 = (blockIdx.x * 256 + threadIdx.x) * 8;
    int m = blockIdx.y;
    if (k8 >= Kp) return;
    float4 v0 = make_float4(0.f, 0.f, 0.f, 0.f);
    float4 v1 = make_float4(0.f, 0.f, 0.f, 0.f);
    if (m < M) {
        const float* base = src + (size_t)m * ldsrc;
        if (k8 < K)     v0 = *reinterpret_cast<const float4*>(base + k8);
        if (k8 + 4 < K) v1 = *reinterpret_cast<const float4*>(base + k8 + 4);
    }
    __half2 a(__float2half_rn(v0.x), __float2half_rn(v0.y));
    __half2 b(__float2half_rn(v0.z), __float2half_rn(v0.w));
    __half2 c(__float2half_rn(v1.x), __float2half_rn(v1.y));
    __half2 d(__float2half_rn(v1.z), __float2half_rn(v1.w));
    uint4 pk;
    pk.x = *reinterpret_cast<uint32_t*>(&a);
    pk.y = *reinterpret_cast<uint32_t*>(&b);
    pk.z = *reinterpret_cast<uint32_t*>(&c);
    pk.w = *reinterpret_cast<uint32_t*>(&d);
    *reinterpret_cast<uint4*>(out + (size_t)m * Kp + k8) = pk;
}

// ================= bf16 3-product HMMA GEMM (recurrence precompute) ============
__global__ __launch_bounds__(256)
void hmma_gemm(const __nv_bfloat16* __restrict__ Ah, const __nv_bfloat16* __restrict__ Al,
               const __nv_bfloat16* __restrict__ Bh, const __nv_bfloat16* __restrict__ Bl,
               int ldka, int ldkb, int kchunks,
               const float* __restrict__ bias, float* __restrict__ out, int ldo,
               int Mlim, int Nlim)
{
    extern __shared__ __align__(16) char smem[];
    const uint32_t sb = smem_u32(smem);
    const int tid = threadIdx.x;
    const int lane = tid & 31;
    const int wid = tid >> 5;
    const int wm = wid & 1;
    const int wn = wid >> 1;
    const int m0 = blockIdx.x * BM;
    const int n0 = blockIdx.y * BN;

    const __nv_bfloat16* srcs[4] = {
        Ah + (size_t)m0 * ldka, Al + (size_t)m0 * ldka,
        Bh + (size_t)n0 * ldkb, Bl + (size_t)n0 * ldkb
    };
    const int lds[4] = { ldka, ldka, ldkb, ldkb };

    auto load_stage = [&](int c, int buf) {
        uint32_t base = sb + buf * STAGE_BYTES;
        int kofs = c * BK;
#pragma unroll
        for (int i = 0; i < 8; i++) {
            int idx = tid + i * 256;
            int tile = idx >> 9;
            int rem = idx & 511;
            int row = rem >> 2;
            int seg = rem & 3;
            const char* g = (const char*)(srcs[tile] + (size_t)row * lds[tile] + kofs) + seg * 16;
            uint32_t so = base + tile * TILE_BYTES + row * (LDSROW * 2) + seg * 16;
            asm volatile("cp.async.cg.shared.global [%0], [%1], 16;\n" :: "r"(so), "l"(g));
        }
        asm volatile("cp.async.commit_group;\n" ::: "memory");
    };

    float acc[4][4][4];
#pragma unroll
    for (int i = 0; i < 4; i++)
#pragma unroll
        for (int j = 0; j < 4; j++)
#pragma unroll
            for (int q = 0; q < 4; q++) acc[i][j][q] = 0.f;

    load_stage(0, 0);

    for (int c = 0; c < kchunks; c++) {
        if (c + 1 < kchunks) {
            load_stage(c + 1, (c + 1) & 1);
            asm volatile("cp.async.wait_group 1;\n" ::: "memory");
        } else {
            asm volatile("cp.async.wait_group 0;\n" ::: "memory");
        }
        __syncthreads();

        uint32_t st = sb + (c & 1) * STAGE_BYTES;
        uint32_t bAh = st;
        uint32_t bAl = st + TILE_BYTES;
        uint32_t bBh = st + 2 * TILE_BYTES;
        uint32_t bBl = st + 3 * TILE_BYTES;

#pragma unroll
        for (int ks = 0; ks < 2; ks++) {
            uint32_t ah[4][4], al[4][4], bh[4][2], bl[4][2];

            int arow = wm * 64 + (lane & 15);
            uint32_t acol = ks * 32 + (lane >> 4) * 16;
#pragma unroll
            for (int mt = 0; mt < 4; mt++) {
                uint32_t off = (uint32_t)(arow + mt * 16) * (LDSROW * 2) + acol;
                ldsm_x4(ah[mt], bAh + off);
                ldsm_x4(al[mt], bAl + off);
            }
            int brow_base = wn * 32 + (lane & 7) + ((lane >> 4) << 3);
            uint32_t bcol = ks * 32 + ((lane >> 3) & 1) * 16;
#pragma unroll
            for (int np = 0; np < 2; np++) {
                uint32_t r[4];
                uint32_t off = (uint32_t)(brow_base + np * 16) * (LDSROW * 2) + bcol;
                ldsm_x4(r, bBh + off);
                bh[np * 2][0] = r[0]; bh[np * 2][1] = r[1];
                bh[np * 2 + 1][0] = r[2]; bh[np * 2 + 1][1] = r[3];
                ldsm_x4(r, bBl + off);
                bl[np * 2][0] = r[0]; bl[np * 2][1] = r[1];
                bl[np * 2 + 1][0] = r[2]; bl[np * 2 + 1][1] = r[3];
            }
#pragma unroll
            for (int mt = 0; mt < 4; mt++)
#pragma unroll
                for (int nt = 0; nt < 4; nt++) {
                    mma_bf16(acc[mt][nt], ah[mt], bh[nt]);
                    mma_bf16(acc[mt][nt], al[mt], bh[nt]);
                    mma_bf16(acc[mt][nt], ah[mt], bl[nt]);
                }
        }
        __syncthreads();
    }

#pragma unroll
    for (int mt = 0; mt < 4; mt++) {
#pragma unroll
        for (int nt = 0; nt < 4; nt++) {
            int m = m0 + wm * 64 + mt * 16 + (lane >> 2);
            int n = n0 + wn * 32 + nt * 8 + 2 * (lane & 3);
            if (n < Nlim) {
                float b0 = 0.f, b1 = 0.f;
                if (bias) { b0 = bias[n]; b1 = bias[n + 1]; }
                if (m < Mlim) {
                    float2 v = make_float2(acc[mt][nt][0] + b0, acc[mt][nt][1] + b1);
                    *reinterpret_cast<float2*>(out + (size_t)m * ldo + n) = v;
                }
                if (m + 8 < Mlim) {
                    float2 v = make_float2(acc[mt][nt][2] + b0, acc[mt][nt][3] + b1);
                    *reinterpret_cast<float2*>(out + (size_t)(m + 8) * ldo + n) = v;
                }
            }
        }
    }
}

// ================= fp16 single-product HMMA GEMM, BK=64, 2-stage ===============
__global__ __launch_bounds__(256)
void hmma_gemm_f16(const __half* __restrict__ A, const __half* __restrict__ B,
                   int kchunks,
                   const float* __restrict__ bias, float* __restrict__ out, int ldo,
                   int Mlim, int Nlim)
{
    extern __shared__ __align__(16) char smem[];
    const uint32_t sb = smem_u32(smem);
    const int tid = threadIdx.x;
    const int lane = tid & 31;
    const int wid = tid >> 5;
    const int wm = wid & 1;
    const int wn = wid >> 1;
    const int m0 = blockIdx.x * BM;
    const int n0 = blockIdx.y * BN;

    const __half* srcs[2] = {
        A + (size_t)m0 * KPAD, B + (size_t)n0 * KPAD
    };

    auto load_stage = [&](int c, int buf) {
        uint32_t base = sb + buf * STAGE2_BYTES;
        int kofs = c * BK2;
#pragma unroll
        for (int i = 0; i < 8; i++) {
            int idx = tid + i * 256;            // 0..2047
            int tile = idx >> 10;
            int rem = idx & 1023;
            int row = rem >> 3;
            int seg = rem & 7;
            const char* g = (const char*)(srcs[tile] + (size_t)row * KPAD + kofs) + seg * 16;
            uint32_t so = base + tile * TILE2_BYTES + row * (LDSROW2 * 2) + seg * 16;
            asm volatile("cp.async.cg.shared.global [%0], [%1], 16;\n" :: "r"(so), "l"(g));
        }
        asm volatile("cp.async.commit_group;\n" ::: "memory");
    };

    float acc[4][4][4];
#pragma unroll
    for (int i = 0; i < 4; i++)
#pragma unroll
        for (int j = 0; j < 4; j++)
#pragma unroll
            for (int q = 0; q < 4; q++) acc[i][j][q] = 0.f;

    load_stage(0, 0);

    for (int c = 0; c < kchunks; c++) {
        if (c + 1 < kchunks) {
            load_stage(c + 1, (c + 1) & 1);
            asm volatile("cp.async.wait_group 1;\n" ::: "memory");
        } else {
            asm volatile("cp.async.wait_group 0;\n" ::: "memory");
        }
        __syncthreads();

        uint32_t st = sb + (c & 1) * STAGE2_BYTES;
        uint32_t bA = st;
        uint32_t bB = st + TILE2_BYTES;

#pragma unroll
        for (int ks = 0; ks < 4; ks++) {
            uint32_t ah[4][4], bh[4][2];

            int arow = wm * 64 + (lane & 15);
            uint32_t acol = ks * 32 + (lane >> 4) * 16;
#pragma unroll
            for (int mt = 0; mt < 4; mt++) {
                uint32_t off = (uint32_t)(arow + mt * 16) * (LDSROW2 * 2) + acol;
                ldsm_x4(ah[mt], bA + off);
            }
            int brow_base = wn * 32 + (lane & 7) + ((lane >> 4) << 3);
            uint32_t bcol = ks * 32 + ((lane >> 3) & 1) * 16;
#pragma unroll
            for (int np = 0; np < 2; np++) {
                uint32_t r[4];
                uint32_t off = (uint32_t)(brow_base + np * 16) * (LDSROW2 * 2) + bcol;
                ldsm_x4(r, bB + off);
                bh[np * 2][0] = r[0]; bh[np * 2][1] = r[1];
                bh[np * 2 + 1][0] = r[2]; bh[np * 2 + 1][1] = r[3];
            }
#pragma unroll
            for (int mt = 0; mt < 4; mt++)
#pragma unroll
                for (int nt = 0; nt < 4; nt++)
                    mma_f16(acc[mt][nt], ah[mt], bh[nt]);
        }
        __syncthreads();
    }

#pragma unroll
    for (int mt = 0; mt < 4; mt++) {
#pragma unroll
        for (int nt = 0; nt < 4; nt++) {
            int m = m0 + wm * 64 + mt * 16 + (lane >> 2);
            int n = n0 + wn * 32 + nt * 8 + 2 * (lane & 3);
            if (n < Nlim) {
                float b0 = bias[n], b1 = bias[n + 1];
                if (m < Mlim) {
                    float2 v = make_float2(acc[mt][nt][0] + b0, acc[mt][nt][1] + b1);
                    *reinterpret_cast<float2*>(out + (size_t)m * ldo + n) = v;
                }
                if (m + 8 < Mlim) {
                    float2 v = make_float2(acc[mt][nt][2] + b0, acc[mt][nt][3] + b1);
                    *reinterpret_cast<float2*>(out + (size_t)(m + 8) * ldo + n) = v;
                }
            }
        }
    }
}

// ---------------- init ----------------
__global__ void zero_kernel(float* __restrict__ preds, float* __restrict__ attns)
{
    int i = blockIdx.x * blockDim.x + threadIdx.x;
    if (i < BATCH * V_DIM) preds[i] = 0.f;
    if (i < S_LEN * BATCH) attns[i] = 0.f;
}

// ---------------- gather embeddings into comb2 emb columns ----------------
__global__ void gather_kernel(const int* __restrict__ tokens,
                              const float* __restrict__ emb,
                              float* __restrict__ comb2)
{
    int r = blockIdx.x;
    int tok = tokens[r];
    const float4* src = reinterpret_cast<const float4*>(emb + (size_t)tok * E_DIM);
    float4* dst = reinterpret_cast<float4*>(comb2 + (size_t)r * C2_DIM);
    int i = threadIdx.x;
    if (i < E_DIM / 4) dst[i] = src[i];
}

// ---------------- h0 = tanh(ann[0,:,ECH:] @ W_h.T + b_h) ----------------
__global__ void h0_kernel(const float* __restrict__ ann, const float* __restrict__ W_h,
                          const float* __restrict__ b_h, float* __restrict__ hbuf,
                          float* __restrict__ comb2)
{
    int w = (blockIdx.x * 256 + threadIdx.x) >> 5;
    if (w >= BATCH * H_DIM) return;
    int lane = threadIdx.x & 31;
    int b = w / H_DIM, n = w - b * H_DIM;
    const float4* a4 = reinterpret_cast<const float4*>(ann + (size_t)b * A_DIM + ECH);
    const float4* w4 = reinterpret_cast<const float4*>(W_h + (size_t)n * H_DIM);
    float s = 0.f;
    for (int i = lane; i < H_DIM / 4; i += 32) {
        float4 x = a4[i], y = w4[i];
        s += x.x * y.x + x.y * y.y + x.z * y.z + x.w * y.w;
    }
    s = warp_sum(s);
    if (lane == 0) {
        float v = tanh_fast(s + b_h[n]);
        hbuf[b * H_DIM + n] = v;
        comb2[(size_t)b * C2_DIM + E_DIM + n] = v;
    }
}

// ---------------- per-step: ug = h @ [Wc_h | W_hh].T (R15 proven config) -------
// 512 threads (16 warps) x 2 rows/warp, grid 125 = one wave, 4000 rows exactly.
#define STEP_SMEM (BATCH * H_DIM * 4)    // 128000 B
__global__ __launch_bounds__(512)
void step_ug2_kernel(const __nv_bfloat16* __restrict__ wh, const __nv_bfloat16* __restrict__ wl,
                     const float* __restrict__ h, float* __restrict__ ug)
{
    extern __shared__ float hsh[];       // [BATCH * H_DIM]
    int tid = threadIdx.x;
    int lane = tid & 31;
    int warp = tid >> 5;

    const float4* h4 = reinterpret_cast<const float4*>(h);
    float4* s4 = reinterpret_cast<float4*>(hsh);
    for (int i = tid; i < BATCH * H_DIM / 4; i += 512) s4[i] = h4[i];
    __syncthreads();

    int r0 = (blockIdx.x * 16 + warp) * 2;       // 0..3998 (grid 125, exact)
    int r1 = r0 + 1;
    int n0 = (r0 < 1000) ? r0 : (r0 + 24);       // stacked-row index
    int n1 = (r1 < 1000) ? r1 : (r1 + 24);

    const __nv_bfloat16* WH0 = wh + (size_t)n0 * 1024;
    const __nv_bfloat16* WL0 = wl + (size_t)n0 * 1024;
    const __nv_bfloat16* WH1 = wh + (size_t)n1 * 1024;
    const __nv_bfloat16* WL1 = wl + (size_t)n1 * 1024;

    float acc0[32], acc1[32];
#pragma unroll
    for (int b = 0; b < 32; b++) { acc0[b] = 0.f; acc1[b] = 0.f; }

    for (int k = lane; k < H_DIM; k += 32) {
        float w0 = __bfloat162float(WH0[k]) + __bfloat162float(WL0[k]);
        float w1 = __bfloat162float(WH1[k]) + __bfloat162float(WL1[k]);
        const float* hp = hsh + k;
#pragma unroll
        for (int b = 0; b < 32; b++) {
            float hv = hp[b * H_DIM];
            acc0[b] = fmaf(w0, hv, acc0[b]);
            acc1[b] = fmaf(w1, hv, acc1[b]);
        }
    }

    float out0 = 0.f, out1 = 0.f;
#pragma unroll
    for (int b = 0; b < 32; b++) {
        float s0 = warp_sum(acc0[b]);
        float s1 = warp_sum(acc1[b]);
        if (lane == b) { out0 = s0; out1 = s1; }
    }
    ug[(size_t)lane * UG_LD + n0] = out0;
    ug[(size_t)lane * UG_LD + n1] = out1;
}

// ---------------- per-step: scores ----------------
__global__ void scores_kernel(const float* __restrict__ att_pre,
                              const float* __restrict__ ug,
                              const float* __restrict__ w_a,
                              float* __restrict__ scores)
{
    int w = (blockIdx.x * blockDim.x + threadIdx.x) >> 5;
    if (w >= S_LEN * BATCH) return;
    int lane = threadIdx.x & 31;
    int b = w & 31;
    const float4* ap = reinterpret_cast<const float4*>(att_pre + (size_t)w * H_DIM);
    const float4* ub = reinterpret_cast<const float4*>(ug + (size_t)b * UG_LD);
    const float4* wa = reinterpret_cast<const float4*>(w_a);
    float s = 0.f;
    for (int i = lane; i < H_DIM / 4; i += 32) {
        float4 p = ap[i], q = ub[i], wv = wa[i];
        s += wv.x * tanh_fast(p.x + q.x) + wv.y * tanh_fast(p.y + q.y)
           + wv.z * tanh_fast(p.z + q.z) + wv.w * tanh_fast(p.w + q.w);
    }
    s = warp_sum(s);
    if (lane == 0) scores[w] = s;
}

// ---------------- per-step fused: softmax + context + GRU gates ----------------
__global__ __launch_bounds__(256)
void ctxgates_kernel(const float* __restrict__ scores,
                     const float* __restrict__ ann,
                     float* __restrict__ attn_out,
                     float* __restrict__ ctx_out,
                     const float* __restrict__ ann_ih,
                     const float* __restrict__ gi_e_t,
                     const float* __restrict__ ug,
                     const float* __restrict__ b_hh,
                     const float* __restrict__ hprev,
                     float* __restrict__ hnew,
                     float* __restrict__ comb2_hnext)   // nullptr on last step
{
    __shared__ float attn_sh[S_LEN * BATCH];
    int tid = threadIdx.x;
    int bid = blockIdx.x;
    int warp = tid >> 5, lane = tid & 31;

    for (int s = warp; s < S_LEN; s += 8) {
        float v = scores[s * BATCH + lane];
        float mx = warp_max(v);
        float e = __expf(v - mx);
        float sm = warp_sum(e);
        float a = e / sm;
        attn_sh[s * BATCH + lane] = a;
        if (bid == 0) attn_out[s * BATCH + lane] = a;
    }
    __syncthreads();

    if (bid < 64) {
#pragma unroll
        for (int r = 0; r < 4; r++) {
            int local = r * 256 + tid;
            if (local < 1000) {
                int g = bid * 1000 + local;
                int b = g / A_DIM, e = g % A_DIM;
                float acc = 0.f;
#pragma unroll 10
                for (int s = 0; s < S_LEN; s++)
                    acc += attn_sh[s * BATCH + b] * ann[((size_t)s * BATCH + b) * A_DIM + e];
                ctx_out[(size_t)b * C2_DIM + (E_DIM + H_DIM) + e] = acc;
            }
        }
    } else {
        int gb = bid - 64;
        int b = gb & 31;
        int jc = gb >> 5;
        int j = jc * 256 + tid;
        if (j >= H_DIM) return;

        float gr = 0.f, gz = 0.f, gn = 0.f;
#pragma unroll 10
        for (int s = 0; s < S_LEN; s++) {
            float a = attn_sh[s * BATCH + b];
            const float* base = ann_ih + ((size_t)s * BATCH + b) * G_DIM;
            gr += a * base[j];
            gz += a * base[H_DIM + j];
            gn += a * base[2 * H_DIM + j];
        }
        const float* ge = gi_e_t + (size_t)b * G_DIM;
        const float* gb_ = ug + (size_t)b * UG_LD + UG_GH;
        float hr = gb_[j] + b_hh[j];
        float hz = gb_[H_DIM + j] + b_hh[H_DIM + j];
        float hn = gb_[2 * H_DIM + j] + b_hh[2 * H_DIM + j];
        float r = 1.f / (1.f + __expf(-(ge[j] + gr + hr)));
        float z = 1.f / (1.f + __expf(-(ge[H_DIM + j] + gz + hz)));
        float n = tanh_fast(ge[2 * H_DIM + j] + gn + r * hn);
        float hp = hprev[(size_t)b * H_DIM + j];
        float v = (1.f - z) * n + z * hp;
        hnew[(size_t)b * H_DIM + j] = v;
        if (comb2_hnext)
            comb2_hnext[(size_t)b * C2_DIM + E_DIM + j] = v;
    }
}

// ---------------- emit hidden output ----------------
__global__ void hidden_kernel(const float* __restrict__ hbuf, float* __restrict__ hidden)
{
    int i = blockIdx.x * blockDim.x + threadIdx.x;
    if (i < BATCH * H_DIM)
        hidden[i] = hbuf[(size_t)NSTEPS * BATCH * H_DIM + i];
}

// ---------------- single-pass row log-softmax ----------------
__global__ __launch_bounds__(512)
void logsoftmax_kernel(float* __restrict__ logits)
{
    extern __shared__ float sh[];
    int r = blockIdx.x;
    float* p = logits + (size_t)r * V_DIM;
    int tid = threadIdx.x;
    int lane = tid & 31, warp = tid >> 5;
    __shared__ float red[16];
    __shared__ float bc[2];

    float mx = -1e30f;
    for (int i = tid; i < V_DIM; i += 512) {
        float v = p[i];
        sh[i] = v;
        mx = fmaxf(mx, v);
    }
    mx = warp_max(mx);
    if (lane == 0) red[warp] = mx;
    __syncthreads();
    if (tid < 32) {
        float v = (tid < 16) ? red[tid] : -1e30f;
        v = warp_max(v);
        if (tid == 0) bc[0] = v;
    }
    __syncthreads();
    mx = bc[0];

    float sm = 0.f;
    for (int i = tid; i < V_DIM; i += 512) sm += __expf(sh[i] - mx);
    sm = warp_sum(sm);
    if (lane == 0) red[warp] = sm;
    __syncthreads();
    if (tid < 32) {
        float v = (tid < 16) ? red[tid] : 0.f;
        v = warp_sum(v);
        if (tid == 0) bc[1] = v;
    }
    __syncthreads();
    float lse = mx + logf(bc[1]);

    for (int i = tid; i < V_DIM; i += 512) p[i] = sh[i] - lse;
}

// ---------------- host launcher ----------------
extern "C" void kernel_launch(void* const* d_in, const int* in_sizes, int n_in,
                              void* d_out, int out_size)
{
    (void)in_sizes; (void)n_in; (void)out_size;
    const int*   tokens = (const int*)  d_in[0];
    const float* ann    = (const float*)d_in[1];
    const float* emb    = (const float*)d_in[2];
    const float* W_h    = (const float*)d_in[3];
    const float* b_h    = (const float*)d_in[4];
    const float* W_c    = (const float*)d_in[5];
    const float* b_c    = (const float*)d_in[6];
    const float* w_a    = (const float*)d_in[7];
    const float* W_ih   = (const float*)d_in[8];
    const float* W_hh   = (const float*)d_in[9];
    const float* b_ih   = (const float*)d_in[10];
    const float* b_hh   = (const float*)d_in[11];
    const float* W_p    = (const float*)d_in[12];
    const float* b_p    = (const float*)d_in[13];

    float* scr = nullptr;
    cudaGetSymbolAddress((void**)&scr, g_scratch);
    __half *aF, *bF;
    __nv_bfloat16 *annS, *wcaS, *wihcS, *wiheS, *embS, *wstepS;
    cudaGetSymbolAddress((void**)&aF,     g_aF);
    cudaGetSymbolAddress((void**)&bF,     g_bF);
    cudaGetSymbolAddress((void**)&annS,   g_annS);
    cudaGetSymbolAddress((void**)&wcaS,   g_wcaS);
    cudaGetSymbolAddress((void**)&wihcS,  g_wihcS);
    cudaGetSymbolAddress((void**)&wiheS,  g_wiheS);
    cudaGetSymbolAddress((void**)&embS,   g_embS);
    cudaGetSymbolAddress((void**)&wstepS, g_wstepS);

    __nv_bfloat16* annL  = annS  + (size_t)1664 * 2048;
    __nv_bfloat16* wcaL  = wcaS  + (size_t)1024 * 2048;
    __nv_bfloat16* wihcL = wihcS + (size_t)3072 * 2048;
    __nv_bfloat16* wiheL = wiheS + (size_t)3072 * 640;
    __nv_bfloat16* embL  = embS  + (size_t)1664 * 640;
    __nv_bfloat16* wstL  = wstepS + (size_t)4096 * 1024;

    float* att_pre = scr + OFF_ATT_PRE;
    float* ann_ih  = scr + OFF_ANN_IH;
    float* gi_e    = scr + OFF_GI_E;
    float* hbuf    = scr + OFF_H;
    float* comb2   = scr + OFF_COMB2;
    float* ug      = scr + OFF_UG;
    float* scbuf   = scr + OFF_SCORES;

    float* preds  = (float*)d_out;
    float* hidden = preds + (size_t)T_LEN * BATCH * V_DIM;
    float* attns  = hidden + BATCH * H_DIM;
    float* predsB = preds + (size_t)BATCH * V_DIM;

    // one-time resource init
    static cudaStream_t s2 = nullptr;
    static cudaEvent_t evFork, evB, evG1, evJoin;
    if (!s2) {
        cudaStreamCreateWithFlags(&s2, cudaStreamNonBlocking);
        cudaEventCreateWithFlags(&evFork, cudaEventDisableTiming);
        cudaEventCreateWithFlags(&evB, cudaEventDisableTiming);
        cudaEventCreateWithFlags(&evG1, cudaEventDisableTiming);
        cudaEventCreateWithFlags(&evJoin, cudaEventDisableTiming);
        cudaFuncSetAttribute(hmma_gemm,
                             cudaFuncAttributeMaxDynamicSharedMemorySize, GEMM_SMEM);
        cudaFuncSetAttribute(hmma_gemm_f16,
                             cudaFuncAttributeMaxDynamicSharedMemorySize, GEMM2_SMEM);
        cudaFuncSetAttribute(logsoftmax_kernel,
                             cudaFuncAttributeMaxDynamicSharedMemorySize, V_DIM * 4);
        cudaFuncSetAttribute(step_ug2_kernel,
                             cudaFuncAttributeMaxDynamicSharedMemorySize, STEP_SMEM);
    }

    // ---- fork: W_p -> fp16 on side stream (overlaps precompute phase) ----
    zero_kernel<<<(BATCH * V_DIM + 255) / 256, 256>>>(preds, attns);
    cudaEventRecord(evFork, 0);
    cudaStreamWaitEvent(s2, evFork, 0);
    split_f16<<<dim3(2, NPAD), 256, 0, s2>>>(W_p, C2_DIM, V_DIM, C2_DIM, KPAD, bF);
    cudaEventRecord(evB, s2);

    // ---- main stream: splits + h0 + precompute ----
    gather_kernel<<<ROWS, 160>>>(tokens, emb, comb2);
    split_gen4<<<dim3(2, 1664), 256>>>(ann, A_DIM, S_LEN * BATCH, A_DIM, 2048, annS, annL);
    split_gen4<<<dim3(2, 1024), 256>>>(W_c + H_DIM, H_DIM + A_DIM, H_DIM, A_DIM, 2048, wcaS, wcaL);
    split_gen4<<<dim3(2, 3072), 256>>>(W_ih + E_DIM, E_DIM + A_DIM, G_DIM, A_DIM, 2048, wihcS, wihcL);
    split_gen4<<<dim3(1, 3072), 256>>>(W_ih, E_DIM + A_DIM, G_DIM, E_DIM, 640, wiheS, wiheL);
    split_gen4<<<dim3(1, 1664), 256>>>(comb2, C2_DIM, ROWS, E_DIM, 640, embS, embL);
    split_gen4<<<dim3(1, 1024), 256>>>(W_c, H_DIM + A_DIM, H_DIM, H_DIM, 1024, wstepS, wstL);
    split_gen4<<<dim3(1, 3072), 256>>>(W_hh, H_DIM, G_DIM, H_DIM, 1024,
                                       wstepS + (size_t)1024 * 1024, wstL + (size_t)1024 * 1024);

    h0_kernel<<<4000, 256>>>(ann, W_h, b_h, hbuf, comb2);

    hmma_gemm<<<dim3(13, 8), 256, GEMM_SMEM>>>(annS, annL, wcaS, wcaL,
        2048, 2048, 64, b_c, att_pre, H_DIM, S_LEN * BATCH, H_DIM);
    hmma_gemm<<<dim3(13, 24), 256, GEMM_SMEM>>>(annS, annL, wihcS, wihcL,
        2048, 2048, 64, nullptr, ann_ih, G_DIM, S_LEN * BATCH, G_DIM);
    hmma_gemm<<<dim3(13, 24), 256, GEMM_SMEM>>>(embS, embL, wiheS, wiheL,
        640, 640, 20, b_ih, gi_e, G_DIM, ROWS, G_DIM);

    // ---- sequential recurrence (3 launches/step, single stream) ----
    for (int i = 0; i < NSTEPS; i++) {
        float* hprev = hbuf + (size_t)i * BATCH * H_DIM;
        float* hnext = hbuf + (size_t)(i + 1) * BATCH * H_DIM;
        float* attn_t = attns + (size_t)(i + 1) * S_LEN * BATCH;
        float* c2h = (i + 1 < NSTEPS) ? comb2 + (size_t)(i + 1) * BATCH * C2_DIM : nullptr;

        step_ug2_kernel<<<125, 512, STEP_SMEM>>>(wstepS, wstL, hprev, ug);
        scores_kernel<<<200, 256>>>(att_pre, ug, w_a, scbuf);
        ctxgates_kernel<<<192, 256>>>(scbuf, ann, attn_t,
                                      comb2 + (size_t)i * BATCH * C2_DIM,
                                      ann_ih, gi_e + (size_t)i * BATCH * G_DIM,
                                      ug, b_hh, hprev, hnext, c2h);
    }

    hidden_kernel<<<(BATCH * H_DIM + 255) / 256, 256>>>(hbuf, hidden);
    split_f16<<<dim3(2, 1664), 256>>>(comb2, C2_DIM, ROWS, C2_DIM, KPAD, aF);

    // ---- prediction GEMM in two M-halves; log-softmax of half 1 overlaps half 2 ----
    cudaStreamWaitEvent(0, evB, 0);          // B (W_p fp16) ready
    hmma_gemm_f16<<<dim3(6, 235), 256, GEMM2_SMEM>>>(aF, bF,
        KPAD / BK2, b_p, predsB, V_DIM, 768, V_DIM);
    cudaEventRecord(evG1, 0);

    hmma_gemm_f16<<<dim3(7, 235), 256, GEMM2_SMEM>>>(aF + (size_t)768 * KPAD, bF,
        KPAD / BK2, b_p, predsB + (size_t)768 * V_DIM, V_DIM, ROWS - 768, V_DIM);

    cudaStreamWaitEvent(s2, evG1, 0);
    logsoftmax_kernel<<<768, 512, V_DIM * 4, s2>>>(predsB);
    cudaEventRecord(evJoin, s2);

    logsoftmax_kernel<<<ROWS - 768, 512, V_DIM * 4>>>(predsB + (size_t)768 * V_DIM);
    cudaStreamWaitEvent(0, evJoin, 0);
}